// round 2
// baseline (speedup 1.0000x reference)
#include <cuda_runtime.h>
#include <cuda_bf16.h>

// Problem constants
#define S 8192
#define D 1024
#define E 64
#define CAP 128
#define SHIFT 4096
static const long long SEC = (long long)S * E * CAP;   // 67108864

// ---------------- scratch (device globals; no allocation allowed) -----------
__device__ float g_logits[S * E];
__device__ int   g_beste[S];
__device__ float g_gmax[S];
__device__ int   g_rank[S];
__device__ int   g_expert_at_p[S];
__device__ int   g_token_at_p[S];
__device__ int   g_hist[S];     // [128 chunks][64 experts]
__device__ int   g_choff[S];    // exclusive prefix per expert over chunks
__device__ float g_me[E];
__device__ int   g_cnt[E];
__device__ int   g_dropped;

// ---------------------------------------------------------------------------
// K1: fused  (blocks 0..127: GEMM logits = x @ w^T)   (blocks 128.. : zero out)
// ---------------------------------------------------------------------------
#define GEMM_BLOCKS 128
#define ZERO_BLOCKS 1024

__global__ void k_gemm_zero(const float* __restrict__ x,
                            const float* __restrict__ w,
                            float* __restrict__ out, long long out_size) {
    if (blockIdx.x < GEMM_BLOCKS) {
        // BM=64, BN=64(all experts), BK=32, 256 threads, 4x4 micro-tile
        __shared__ float As[32][64];   // [k][m]
        __shared__ float Bs[32][64];   // [k][e]
        const int m0  = blockIdx.x * 64;
        const int tid = threadIdx.x;
        const int tx  = tid & 15;      // expert group (4 experts each)
        const int ty  = tid >> 4;      // row group    (4 rows each)
        float acc[4][4];
        #pragma unroll
        for (int i = 0; i < 4; i++)
            #pragma unroll
            for (int j = 0; j < 4; j++) acc[i][j] = 0.0f;

        for (int k0 = 0; k0 < D; k0 += 32) {
            #pragma unroll
            for (int r = 0; r < 8; r++) {
                int l  = tid + r * 256;
                int mm = l & 63;
                int kk = l >> 6;
                As[kk][mm] = x[(long long)(m0 + mm) * D + k0 + kk];
                Bs[kk][mm] = w[(long long)mm * D + k0 + kk];
            }
            __syncthreads();
            #pragma unroll
            for (int kk = 0; kk < 32; kk++) {
                const float4 a = *(const float4*)(&As[kk][ty * 4]);
                const float4 b = *(const float4*)(&Bs[kk][tx * 4]);
                float av[4] = {a.x, a.y, a.z, a.w};
                float bv[4] = {b.x, b.y, b.z, b.w};
                #pragma unroll
                for (int i = 0; i < 4; i++)
                    #pragma unroll
                    for (int j = 0; j < 4; j++)
                        acc[i][j] += av[i] * bv[j];
            }
            __syncthreads();
        }
        #pragma unroll
        for (int i = 0; i < 4; i++) {
            float4 v = make_float4(acc[i][0], acc[i][1], acc[i][2], acc[i][3]);
            *(float4*)(&g_logits[(long long)(m0 + ty * 4 + i) * E + tx * 4]) = v;
        }
    } else {
        // zero-fill the whole output buffer (poisoned to 0xAA)
        long long n4 = out_size >> 2;
        float4* o4 = (float4*)out;
        const float4 z = make_float4(0.f, 0.f, 0.f, 0.f);
        long long idx    = (long long)(blockIdx.x - GEMM_BLOCKS) * blockDim.x + threadIdx.x;
        long long stride = (long long)(gridDim.x - GEMM_BLOCKS) * blockDim.x;
        for (; idx < n4; idx += stride) o4[idx] = z;
        if (blockIdx.x == GEMM_BLOCKS) {
            for (long long i = (n4 << 2) + threadIdx.x; i < out_size; i += blockDim.x)
                out[i] = 0.0f;
            // zero scratch that is accumulated into
            for (int i = threadIdx.x; i < S; i += blockDim.x) {
                g_rank[i] = 0;
                g_hist[i] = 0;
            }
            if (threadIdx.x < E) { g_me[threadIdx.x] = 0.0f; g_cnt[threadIdx.x] = 0; }
            if (threadIdx.x == 0) g_dropped = 0;
        }
    }
}

// ---------------------------------------------------------------------------
// K2: softmax + argmax per token (one warp per token), accumulate me / counts
// ---------------------------------------------------------------------------
__global__ void k_softmax() {
    __shared__ float sme[E];
    __shared__ int   scnt[E];
    const int warp = threadIdx.x >> 5;
    const int lane = threadIdx.x & 31;
    const int t = blockIdx.x * 8 + warp;
    if (threadIdx.x < E) { sme[threadIdx.x] = 0.0f; scnt[threadIdx.x] = 0; }
    __syncthreads();

    float l0 = g_logits[(long long)t * E + lane];
    float l1 = g_logits[(long long)t * E + 32 + lane];
    // local best, tie -> smaller index
    float bv; int bi;
    if (l0 >= l1) { bv = l0; bi = lane; } else { bv = l1; bi = lane + 32; }
    #pragma unroll
    for (int o = 16; o; o >>= 1) {
        float ov = __shfl_xor_sync(0xffffffff, bv, o);
        int   oi = __shfl_xor_sync(0xffffffff, bi, o);
        if (ov > bv || (ov == bv && oi < bi)) { bv = ov; bi = oi; }
    }
    float e0 = expf(l0 - bv);
    float e1 = expf(l1 - bv);
    float s = e0 + e1;
    #pragma unroll
    for (int o = 16; o; o >>= 1) s += __shfl_xor_sync(0xffffffff, s, o);
    float inv = 1.0f / s;
    atomicAdd(&sme[lane],      e0 * inv);
    atomicAdd(&sme[lane + 32], e1 * inv);
    if (lane == 0) {
        g_beste[t] = bi;
        g_gmax[t]  = inv;          // max gate = exp(0)/sum
        atomicAdd(&scnt[bi], 1);
    }
    __syncthreads();
    if (threadIdx.x < E) {
        atomicAdd(&g_me[threadIdx.x],  sme[threadIdx.x]);
        atomicAdd(&g_cnt[threadIdx.x], scnt[threadIdx.x]);
    }
}

// ---------------------------------------------------------------------------
// K3: rank by counting (stable argsort of -gmax), split over 8 u-slices
// rank(t) = #{u<t: gmax[u] >= gmax[t]} + #{u>=t: gmax[u] > gmax[t]}
// ---------------------------------------------------------------------------
__global__ void k_rank() {
    __shared__ float sh[1024];
    const int t = blockIdx.x * 256 + threadIdx.x;
    const int ubase = blockIdx.y * 1024;
    for (int i = threadIdx.x; i < 1024; i += 256) sh[i] = g_gmax[ubase + i];
    __syncthreads();
    const float g = g_gmax[t];
    int lo = t - ubase;
    if (lo < 0) lo = 0;
    if (lo > 1024) lo = 1024;
    int cnt = 0;
    for (int j = 0; j < lo; j++)    cnt += (sh[j] >= g);
    for (int j = lo; j < 1024; j++) cnt += (sh[j] >  g);
    atomicAdd(&g_rank[t], cnt);
}

// K3b: rolled priority position, scatter expert/token by position, histogram
__global__ void k_position() {
    const int t = blockIdx.x * 256 + threadIdx.x;
    const int p = (g_rank[t] + SHIFT) & (S - 1);
    const int e = g_beste[t];
    g_expert_at_p[p] = e;
    g_token_at_p[p]  = t;
    atomicAdd(&g_hist[(p >> 6) * E + e], 1);
}

// K4: exclusive prefix over 128 chunks, per expert
__global__ void k_prefix() {
    __shared__ int sh[S];
    for (int i = threadIdx.x; i < S; i += blockDim.x) sh[i] = g_hist[i];
    __syncthreads();
    if (threadIdx.x < E) {
        int run = 0;
        #pragma unroll 1
        for (int b = 0; b < 128; b++) {
            int v = sh[b * E + threadIdx.x];
            g_choff[b * E + threadIdx.x] = run;
            run += v;
        }
    }
}

// ---------------------------------------------------------------------------
// K5: per-chunk within-chunk rank + sparse scatter of combine/dispatch
// ---------------------------------------------------------------------------
__global__ void k_scatter(float* __restrict__ out) {
    __shared__ int se[64];
    const int i = threadIdx.x;
    const int p = blockIdx.x * 64 + i;
    const int e = g_expert_at_p[p];
    const int t = g_token_at_p[p];
    se[i] = e;
    __syncthreads();
    int c = 0;
    for (int j = 0; j < i; j++) c += (se[j] == e);
    const int loc = g_choff[blockIdx.x * E + e] + c;
    if (loc < CAP) {
        long long base = 1LL + ((long long)t * E + e) * CAP + loc;
        float gv = g_gmax[t];
        out[base]       = gv;     // combine_weights
        out[base + SEC] = 1.0f;   // dispatch_mask
    } else {
        atomicAdd(&g_dropped, 1);
    }
}

// K6: scalars + exp_counts
__global__ void k_finalize(float* __restrict__ out) {
    __shared__ float red[E];
    const int e = threadIdx.x;
    const float inv = 1.0f / (float)S;
    red[e] = (g_me[e] * inv) * ((float)g_cnt[e] * inv);
    __syncthreads();
    out[1LL + 2LL * SEC + e] = (float)g_cnt[e];
    if (e == 0) {
        float sum = 0.0f;
        for (int k = 0; k < E; k++) sum += red[k];
        out[0] = sum * (float)E * 0.01f;
        out[1LL + 2LL * SEC + E] = (float)g_dropped * inv;
    }
}

// ---------------------------------------------------------------------------
extern "C" void kernel_launch(void* const* d_in, const int* in_sizes, int n_in,
                              void* d_out, int out_size) {
    const float* x = (const float*)d_in[0];   // [S, D]
    const float* w = (const float*)d_in[1];   // [E, D]
    float* out = (float*)d_out;
    long long osz = (long long)out_size;

    k_gemm_zero<<<GEMM_BLOCKS + ZERO_BLOCKS, 256>>>(x, w, out, osz);
    k_softmax<<<S / 8, 256>>>();
    k_rank<<<dim3(S / 256, 8), 256>>>();
    k_position<<<S / 256, 256>>>();
    k_prefix<<<1, 256>>>();
    k_scatter<<<S / 64, 64>>>(out);
    k_finalize<<<1, E>>>(out);
}